// round 2
// baseline (speedup 1.0000x reference)
#include <cuda_runtime.h>
#include <cuda_bf16.h>

#define WAY   5
#define NQ    75
#define CIN   640
#define NTOK  512
#define CP    64
#define PAIRS (WAY*NQ)          /* 375 */
#define BN_EPS 1e-5f
#define GN_EPS 1e-5f
#define L2_EPS 1e-8f
#define LOG2E  1.4426950408889634f

/* ------------- scratch (device globals: the sanctioned no-alloc workaround) ------------- */
__device__ float g_S[WAY*CP*NTOK];        // projected+normalized support  [w][64][512]
__device__ float g_Q[NQ*CP*NTOK];         // projected+normalized query    [q][64][512]
__device__ float g_mS[WAY*NTOK];          // channel means of raw support  [w][512]
__device__ float g_mQ[NQ*NTOK];           // channel means of raw query    [q][512]
__device__ float g_C[(size_t)PAIRS*NTOK*NTOK];   // correlation tiles (393 MB)
__device__ float g_cm[PAIRS*NTOK];        // per-pair column mean (over i)
__device__ float g_ci[PAIRS*NTOK];        // per-pair column LOG2E/(5*std)
__device__ float g_rm[PAIRS*NTOK];        // per-pair row mean (over k)
__device__ float g_ri[PAIRS*NTOK];        // per-pair row LOG2E/(5*std)
__device__ float g_as[PAIRS*NTOK];        // attn_s [pair][i]
__device__ float g_aq[PAIRS*NTOK];        // attn_q [pair][k]
__device__ float g_wsum[CP];
__device__ float g_scale[CP];
__device__ float g_bias[CP];

__device__ __forceinline__ float ex2(float x) {
    float y;
    asm("ex2.approx.ftz.f32 %0, %1;" : "=f"(y) : "f"(x));
    return y;
}

__device__ __forceinline__ float warp_sum(float v) {
    #pragma unroll
    for (int o = 16; o; o >>= 1) v += __shfl_xor_sync(0xffffffffu, v, o);
    return v;
}

/* ------------- K-pre: BN fold + weight row sums ------------- */
__global__ void kpre(const float* __restrict__ W, const float* __restrict__ gamma,
                     const float* __restrict__ beta, const float* __restrict__ mean,
                     const float* __restrict__ var) {
    int o = threadIdx.x;
    if (o < CP) {
        float s = 0.f;
        for (int c = 0; c < CIN; c++) s += W[o*CIN + c];
        g_wsum[o] = s;
        float sc = gamma[o] * rsqrtf(var[o] + BN_EPS);
        g_scale[o] = sc;
        g_bias[o]  = beta[o] - mean[o] * sc;
    }
}

/* ------------- K0: projection (center + conv + BN + relu + L2 over 64 ch) ----------
 * grid = 80 batches * 4 column tiles; block = 256; tile = [64 out x 128 cols], K=640
 */
__global__ __launch_bounds__(256) void kproj(const float* __restrict__ sup,
                                             const float* __restrict__ qry,
                                             const float* __restrict__ W) {
    __shared__ float ws[32][65];       // padded: conflict-free transpose store
    __shared__ float xs[32][128];
    __shared__ float minv[128];
    __shared__ float psum[16][128];
    __shared__ float linv[128];

    int b  = blockIdx.x >> 2;
    int n0 = (blockIdx.x & 3) * 128;
    const float* x  = (b < WAY) ? sup + (size_t)b*CIN*NTOK : qry + (size_t)(b-WAY)*CIN*NTOK;
    float* outp     = (b < WAY) ? g_S + b*CP*NTOK          : g_Q + (b-WAY)*CP*NTOK;
    float* moutp    = (b < WAY) ? g_mS + b*NTOK            : g_mQ + (b-WAY)*NTOK;

    int t  = threadIdx.x;
    int tx = t & 15, ty = t >> 4;

    float acc[4][8];
    #pragma unroll
    for (int u = 0; u < 4; u++)
        #pragma unroll
        for (int v = 0; v < 8; v++) acc[u][v] = 0.f;
    float cs = 0.f;   // column-sum partial (valid for t<128)

    for (int cc = 0; cc < CIN; cc += 32) {
        for (int j = t; j < 32*64; j += 256) {
            int o = j >> 5, cr = j & 31;
            ws[cr][o] = W[o*CIN + cc + cr];
        }
        for (int j = t; j < 32*128; j += 256) {
            int r = j >> 7, col = j & 127;
            xs[r][col] = x[(size_t)(cc + r)*NTOK + n0 + col];
        }
        __syncthreads();
        if (t < 128) {
            #pragma unroll 8
            for (int r = 0; r < 32; r++) cs += xs[r][t];
        }
        #pragma unroll 4
        for (int kc = 0; kc < 32; kc++) {
            float a[4], bb[8];
            #pragma unroll
            for (int u = 0; u < 4; u++) a[u] = ws[kc][ty*4 + u];
            #pragma unroll
            for (int v = 0; v < 8; v++) bb[v] = xs[kc][tx*8 + v];
            #pragma unroll
            for (int u = 0; u < 4; u++)
                #pragma unroll
                for (int v = 0; v < 8; v++)
                    acc[u][v] = fmaf(a[u], bb[v], acc[u][v]);
        }
        __syncthreads();
    }
    if (t < 128) minv[t] = cs * (1.f/CIN);
    __syncthreads();

    // epilogue: center-correction, BN, relu, accumulate sumsq per column
    float ssq[8];
    #pragma unroll
    for (int v = 0; v < 8; v++) ssq[v] = 0.f;
    #pragma unroll
    for (int u = 0; u < 4; u++) {
        int o = ty*4 + u;
        float wsm = g_wsum[o], sc = g_scale[o], bi = g_bias[o];
        #pragma unroll
        for (int v = 0; v < 8; v++) {
            float y = acc[u][v] - wsm * minv[tx*8 + v];
            y = fmaxf(y * sc + bi, 0.f);
            acc[u][v] = y;
            ssq[v] += y * y;
        }
    }
    #pragma unroll
    for (int v = 0; v < 8; v++) psum[ty][tx*8 + v] = ssq[v];
    __syncthreads();
    if (t < 128) {
        float s = 0.f;
        #pragma unroll
        for (int r = 0; r < 16; r++) s += psum[r][t];
        linv[t] = 1.f / fmaxf(sqrtf(s), L2_EPS);
        moutp[n0 + t] = minv[t];
    }
    __syncthreads();
    #pragma unroll
    for (int u = 0; u < 4; u++) {
        int o = ty*4 + u;
        #pragma unroll
        for (int v = 0; v < 8; v += 4) {
            float4 st;
            st.x = acc[u][v+0] * linv[tx*8 + v+0];
            st.y = acc[u][v+1] * linv[tx*8 + v+1];
            st.z = acc[u][v+2] * linv[tx*8 + v+2];
            st.w = acc[u][v+3] * linv[tx*8 + v+3];
            *(float4*)(outp + (size_t)o*NTOK + n0 + tx*8 + v) = st;
        }
    }
}

/* ------------- K1: per-pair 512x512xK=64 GEMM + row/col stats ------------- */
#define K1_SMEM (64*512*4 + 64*128*4 + 16*128*4 + 4*512*4)   /* 180224 B */

extern "C" __global__ void __launch_bounds__(256, 1) kcorr() {
    extern __shared__ float sm[];
    float* Ssh    = sm;                    // [64][512]
    float* Qsh    = Ssh + 64*512;          // [64][128]
    float* red    = Qsh + 64*128;          // [16][128]
    float* colsum = red + 16*128;          // [512]
    float* colsq  = colsum + 512;
    float* rowsum = colsq  + 512;
    float* rowsq  = rowsum + 512;

    int pair = blockIdx.x;
    int q = pair / WAY, w = pair % WAY;
    const float* Sg = g_S + (size_t)w*CP*NTOK;
    const float* Qg = g_Q + (size_t)q*CP*NTOK;
    float* Cbase = g_C + (size_t)pair*NTOK*NTOK;

    int t = threadIdx.x;
    int tx = t & 15, ty = t >> 4;

    for (int j = t; j < 64*512; j += 256) Ssh[j] = Sg[j];
    for (int j = t; j < 512;    j += 256) { colsum[j] = 0.f; colsq[j] = 0.f; }
    __syncthreads();

    for (int ib = 0; ib < 4; ib++) {
        float rs[8], rq[8];
        #pragma unroll
        for (int u = 0; u < 8; u++) { rs[u] = 0.f; rq[u] = 0.f; }

        for (int kb = 0; kb < 4; kb++) {
            __syncthreads();  // protect Qsh + red from previous iteration readers
            for (int j = t; j < 64*128; j += 256) {
                int c = j >> 7, col = j & 127;
                Qsh[j] = Qg[(size_t)c*NTOK + kb*128 + col];
            }
            __syncthreads();

            float acc[8][8];
            #pragma unroll
            for (int u = 0; u < 8; u++)
                #pragma unroll
                for (int v = 0; v < 8; v++) acc[u][v] = 0.f;

            #pragma unroll 4
            for (int kc = 0; kc < 64; kc++) {
                float a[8], bb[8];
                #pragma unroll
                for (int u = 0; u < 8; u++) a[u]  = Ssh[kc*512 + ib*128 + ty*8 + u];
                #pragma unroll
                for (int v = 0; v < 8; v++) bb[v] = Qsh[kc*128 + tx*8 + v];
                #pragma unroll
                for (int u = 0; u < 8; u++)
                    #pragma unroll
                    for (int v = 0; v < 8; v++)
                        acc[u][v] = fmaf(a[u], bb[v], acc[u][v]);
            }

            // store C subtile (float4 x2 per row)
            float* cp = Cbase + (size_t)(ib*128 + ty*8)*NTOK + kb*128 + tx*8;
            #pragma unroll
            for (int u = 0; u < 8; u++) {
                float4 v0 = make_float4(acc[u][0], acc[u][1], acc[u][2], acc[u][3]);
                float4 v1 = make_float4(acc[u][4], acc[u][5], acc[u][6], acc[u][7]);
                *(float4*)(cp + (size_t)u*NTOK)     = v0;
                *(float4*)(cp + (size_t)u*NTOK + 4) = v1;
            }

            // stats partials
            float cv[8], cvq[8];
            #pragma unroll
            for (int v = 0; v < 8; v++) { cv[v] = 0.f; cvq[v] = 0.f; }
            #pragma unroll
            for (int u = 0; u < 8; u++)
                #pragma unroll
                for (int v = 0; v < 8; v++) {
                    float a = acc[u][v];
                    rs[u] += a;  rq[u] += a*a;
                    cv[v] += a;  cvq[v] += a*a;
                }

            #pragma unroll
            for (int v = 0; v < 8; v++) red[ty*128 + tx*8 + v] = cv[v];
            __syncthreads();
            if (t < 128) {
                float s = 0.f;
                #pragma unroll
                for (int r = 0; r < 16; r++) s += red[r*128 + t];
                colsum[kb*128 + t] += s;
            }
            __syncthreads();
            #pragma unroll
            for (int v = 0; v < 8; v++) red[ty*128 + tx*8 + v] = cvq[v];
            __syncthreads();
            if (t < 128) {
                float s = 0.f;
                #pragma unroll
                for (int r = 0; r < 16; r++) s += red[r*128 + t];
                colsq[kb*128 + t] += s;
            }
        }

        __syncthreads();
        #pragma unroll
        for (int u = 0; u < 8; u++) red[tx*128 + ty*8 + u] = rs[u];
        __syncthreads();
        if (t < 128) {
            float s = 0.f;
            #pragma unroll
            for (int r = 0; r < 16; r++) s += red[r*128 + t];
            rowsum[ib*128 + t] = s;
        }
        __syncthreads();
        #pragma unroll
        for (int u = 0; u < 8; u++) red[tx*128 + ty*8 + u] = rq[u];
        __syncthreads();
        if (t < 128) {
            float s = 0.f;
            #pragma unroll
            for (int r = 0; r < 16; r++) s += red[r*128 + t];
            rowsq[ib*128 + t] = s;
        }
        __syncthreads();
    }

    // finalize stats: mean and LOG2E/(5*sqrt(var_ddof1 + eps))
    for (int j = t; j < 512; j += 256) {
        float s = colsum[j], sq = colsq[j];
        float m = s * (1.f/512.f);
        float var = fmaxf(sq - s*m, 0.f) * (1.f/511.f);
        g_cm[pair*NTOK + j] = m;
        g_ci[pair*NTOK + j] = LOG2E / (5.f * sqrtf(var + GN_EPS));
        s = rowsum[j]; sq = rowsq[j];
        m = s * (1.f/512.f);
        var = fmaxf(sq - s*m, 0.f) * (1.f/511.f);
        g_rm[pair*NTOK + j] = m;
        g_ri[pair*NTOK + j] = LOG2E / (5.f * sqrtf(var + GN_EPS));
    }
}

/* ------------- K2: per-pair bidirectional softmax sums (2 passes over C) -------------
 * 256 threads; thread t owns columns {2t, 2t+1}. Row reductions go through a
 * 32-row smem chunk transpose (no shfl chains). Softmax shift-invariance lets
 * us fold (c - m)*s into fma(c, s, -m*s).
 */
__global__ __launch_bounds__(256) void kattn() {
    __shared__ float ri_s[512], rofs_s[512];     // row inv-scale, row m*s
    __shared__ float rzq[512];                   // 1 / Z_q per row
    __shared__ float rowbuf[32][257];
    __shared__ float part[32][8];

    int pair = blockIdx.x;
    int t = threadIdx.x;
    int r32 = t & 31, g8 = t >> 5;

    for (int j = t; j < 512; j += 256) {
        float m = g_rm[pair*NTOK + j], s = g_ri[pair*NTOK + j];
        ri_s[j] = s;  rofs_s[j] = m * s;
    }
    // this thread's two columns
    float cix = g_ci[pair*NTOK + 2*t],   cmx = g_cm[pair*NTOK + 2*t]   * cix;
    float ciy = g_ci[pair*NTOK + 2*t+1], cmy = g_cm[pair*NTOK + 2*t+1] * ciy;
    __syncthreads();

    const float2* C2 = (const float2*)(g_C + (size_t)pair*NTOK*NTOK);

    /* ---- pass A: Z_s per column (thread-local), Z_q per row (chunked) ---- */
    float zs0 = 0.f, zs1 = 0.f;
    for (int i0 = 0; i0 < 512; i0 += 32) {
        #pragma unroll 8
        for (int r = 0; r < 32; r++) {
            float2 c = C2[(size_t)(i0 + r)*256 + t];
            float es0 = ex2(fmaf(c.x, cix, -cmx));
            float es1 = ex2(fmaf(c.y, ciy, -cmy));
            float rs = ri_s[i0 + r], ro = rofs_s[i0 + r];
            float eq0 = ex2(fmaf(c.x, rs, -ro));
            float eq1 = ex2(fmaf(c.y, rs, -ro));
            zs0 += es0; zs1 += es1;
            rowbuf[r][t] = eq0 + eq1;
        }
        __syncthreads();
        {
            float s = 0.f;
            #pragma unroll 8
            for (int j = 0; j < 32; j++) s += rowbuf[r32][g8*32 + j];
            part[r32][g8] = s;
        }
        __syncthreads();
        if (t < 32) {
            float z = 0.f;
            #pragma unroll
            for (int g = 0; g < 8; g++) z += part[t][g];
            rzq[i0 + t] = 1.f / z;
        }
        __syncthreads();
    }
    float rz0 = 1.f / zs0, rz1 = 1.f / zs1;

    /* ---- pass B: attn_q per column (thread-local), attn_s per row (chunked) ---- */
    float aq0 = 0.f, aq1 = 0.f;
    for (int i0 = 0; i0 < 512; i0 += 32) {
        #pragma unroll 8
        for (int r = 0; r < 32; r++) {
            float2 c = C2[(size_t)(i0 + r)*256 + t];
            float es0 = ex2(fmaf(c.x, cix, -cmx));
            float es1 = ex2(fmaf(c.y, ciy, -cmy));
            float rs = ri_s[i0 + r], ro = rofs_s[i0 + r];
            float eq0 = ex2(fmaf(c.x, rs, -ro));
            float eq1 = ex2(fmaf(c.y, rs, -ro));
            float rq = rzq[i0 + r];
            aq0 = fmaf(eq0, rq, aq0);
            aq1 = fmaf(eq1, rq, aq1);
            rowbuf[r][t] = fmaf(es0, rz0, es1 * rz1);
        }
        __syncthreads();
        {
            float s = 0.f;
            #pragma unroll 8
            for (int j = 0; j < 32; j++) s += rowbuf[r32][g8*32 + j];
            part[r32][g8] = s;
        }
        __syncthreads();
        if (t < 32) {
            float s = 0.f;
            #pragma unroll
            for (int g = 0; g < 8; g++) s += part[t][g];
            g_as[pair*NTOK + i0 + t] = s;
        }
        __syncthreads();
    }
    g_aq[pair*NTOK + 2*t]   = aq0;
    g_aq[pair*NTOK + 2*t+1] = aq1;
}

/* ------------- K3: attention-weighted pooling + cosine sim ------------- */
__global__ __launch_bounds__(256) void kfinal(const float* __restrict__ sup,
                                              const float* __restrict__ qry,
                                              float* __restrict__ out) {
    __shared__ float as_[512], aq_[512], ms[512], mq[512];
    __shared__ float ps[CIN], pq[CIN];
    __shared__ float rbuf[256];

    int pair = blockIdx.x;
    int q = pair / WAY, w = pair % WAY;
    int t = threadIdx.x, warp = t >> 5, lane = t & 31;

    for (int j = t; j < 512; j += 256) {
        as_[j] = g_as[pair*NTOK + j];
        aq_[j] = g_aq[pair*NTOK + j];
        ms[j]  = g_mS[w*NTOK + j];
        mq[j]  = g_mQ[q*NTOK + j];
    }
    __syncthreads();

    const float* xs = sup + (size_t)w*CIN*NTOK;
    const float* xq = qry + (size_t)q*CIN*NTOK;

    for (int c = warp; c < CIN; c += 8) {
        float v = 0.f, v2 = 0.f;
        #pragma unroll 4
        for (int i = lane; i < 512; i += 32) {
            v  += as_[i] * (xs[(size_t)c*NTOK + i] - ms[i]);
            v2 += aq_[i] * (xq[(size_t)c*NTOK + i] - mq[i]);
        }
        v  = warp_sum(v);
        v2 = warp_sum(v2);
        if (lane == 0) { ps[c] = v; pq[c] = v2; }
    }
    __syncthreads();

    float dp = 0.f, ns = 0.f, nq2 = 0.f;
    for (int c = t; c < CIN; c += 256) {
        float a = ps[c], b = pq[c];
        dp += a*b; ns += a*a; nq2 += b*b;
    }
    float vals[3] = {dp, ns, nq2};
    float red3[3];
    for (int r = 0; r < 3; r++) {
        rbuf[t] = vals[r];
        __syncthreads();
        for (int s = 128; s > 0; s >>= 1) {
            if (t < s) rbuf[t] += rbuf[t + s];
            __syncthreads();
        }
        red3[r] = rbuf[0];
        __syncthreads();
    }
    if (t == 0) {
        float psn = fmaxf(sqrtf(red3[1]) * (1.f/512.f), L2_EPS);
        float pqn = fmaxf(sqrtf(red3[2]) * (1.f/512.f), L2_EPS);
        float sim = (red3[0] * (1.f/(512.f*512.f))) / (psn * pqn);
        out[pair] = sim * 5.f;   // / TEMP (0.2)
    }
}

/* ------------- launcher ------------- */
extern "C" void kernel_launch(void* const* d_in, const int* in_sizes, int n_in,
                              void* d_out, int out_size) {
    const float* sup   = (const float*)d_in[0];
    const float* qry   = (const float*)d_in[1];
    const float* W     = (const float*)d_in[2];
    const float* gamma = (const float*)d_in[3];
    const float* beta  = (const float*)d_in[4];
    const float* mean  = (const float*)d_in[5];
    const float* var   = (const float*)d_in[6];
    float* out = (float*)d_out;

    cudaFuncSetAttribute(kcorr, cudaFuncAttributeMaxDynamicSharedMemorySize, K1_SMEM);

    kpre<<<1, 64>>>(W, gamma, beta, mean, var);
    kproj<<<(WAY+NQ)*4, 256>>>(sup, qry, W);
    kcorr<<<PAIRS, 256, K1_SMEM>>>();
    kattn<<<PAIRS, 256>>>();
    kfinal<<<PAIRS, 256>>>(sup, qry, out);
}

// round 3
// speedup vs baseline: 1.3331x; 1.3331x over previous
#include <cuda_runtime.h>
#include <cuda_bf16.h>

#define WAY   5
#define NQ    75
#define CIN   640
#define NTOK  512
#define CP    64
#define PAIRS (WAY*NQ)          /* 375 */
#define BN_EPS 1e-5f
#define GN_EPS 1e-5f
#define L2_EPS 1e-8f
#define LOG2E  1.4426950408889634f

/* scratch (device globals: sanctioned no-alloc workaround)
 * g_S/g_Q layout: [batch][tok 512][ch 64], channels PERMUTED by perm8()
 * so that tf32 mma fragments load as contiguous 8B pairs (c, c+4). */
__device__ float g_S[WAY*NTOK*CP];
__device__ float g_Q[NQ*NTOK*CP];
__device__ float g_mS[WAY*NTOK];
__device__ float g_mQ[NQ*NTOK];
__device__ float g_C[(size_t)PAIRS*NTOK*NTOK];   // 393 MB
__device__ float g_cm[PAIRS*NTOK];
__device__ float g_ci[PAIRS*NTOK];
__device__ float g_rm[PAIRS*NTOK];
__device__ float g_ri[PAIRS*NTOK];
__device__ float g_as[PAIRS*NTOK];
__device__ float g_aq[PAIRS*NTOK];
__device__ float g_wsum[CP];
__device__ float g_scale[CP];
__device__ float g_bias[CP];

__device__ __forceinline__ float ex2(float x) {
    float y;
    asm("ex2.approx.ftz.f32 %0, %1;" : "=f"(y) : "f"(x));
    return y;
}
__device__ __forceinline__ float warp_sum(float v) {
    #pragma unroll
    for (int o = 16; o; o >>= 1) v += __shfl_xor_sync(0xffffffffu, v, o);
    return v;
}
__device__ __forceinline__ unsigned to_tf32(float f) {
    unsigned u;
    asm("cvt.rna.tf32.f32 %0, %1;" : "=r"(u) : "f"(f));
    return u;
}
/* channel permutation: within each 8-group place (m, m+4) adjacent at (2m, 2m+1) */
__device__ __forceinline__ int perm8(int c) {
    return (c & ~7) | ((c & 3) * 2) | ((c >> 2) & 1);
}
__device__ __forceinline__ void mma_tf32(float* d, unsigned a0, unsigned a1,
                                         unsigned a2, unsigned a3,
                                         unsigned b0, unsigned b1) {
    asm volatile(
        "mma.sync.aligned.m16n8k8.row.col.f32.tf32.tf32.f32 "
        "{%0,%1,%2,%3}, {%4,%5,%6,%7}, {%8,%9}, {%0,%1,%2,%3};"
        : "+f"(d[0]), "+f"(d[1]), "+f"(d[2]), "+f"(d[3])
        : "r"(a0), "r"(a1), "r"(a2), "r"(a3), "r"(b0), "r"(b1));
}

/* ------------- K-pre: BN fold + weight row sums ------------- */
__global__ void kpre(const float* __restrict__ W, const float* __restrict__ gamma,
                     const float* __restrict__ beta, const float* __restrict__ mean,
                     const float* __restrict__ var) {
    int o = threadIdx.x;
    if (o < CP) {
        float s = 0.f;
        for (int c = 0; c < CIN; c++) s += W[o*CIN + c];
        g_wsum[o] = s;
        float sc = gamma[o] * rsqrtf(var[o] + BN_EPS);
        g_scale[o] = sc;
        g_bias[o]  = beta[o] - mean[o] * sc;
    }
}

/* ------------- K0: projection, writes transposed+permuted [tok][64] ------------- */
__global__ __launch_bounds__(256) void kproj(const float* __restrict__ sup,
                                             const float* __restrict__ qry,
                                             const float* __restrict__ W) {
    __shared__ float pool[128*68];     // aliased: ws+xs during GEMM, psum then stage after
    __shared__ float minv[128];
    __shared__ float linv[128];
    float* ws = pool;                  // [32][65]
    float* xs = pool + 32*65;          // [32][128]

    int b  = blockIdx.x >> 2;
    int n0 = (blockIdx.x & 3) * 128;
    const float* x  = (b < WAY) ? sup + (size_t)b*CIN*NTOK : qry + (size_t)(b-WAY)*CIN*NTOK;
    float* outp     = (b < WAY) ? g_S + b*NTOK*CP          : g_Q + (b-WAY)*NTOK*CP;
    float* moutp    = (b < WAY) ? g_mS + b*NTOK            : g_mQ + (b-WAY)*NTOK;

    int t  = threadIdx.x;
    int tx = t & 15, ty = t >> 4;

    float acc[4][8];
    #pragma unroll
    for (int u = 0; u < 4; u++)
        #pragma unroll
        for (int v = 0; v < 8; v++) acc[u][v] = 0.f;
    float cs = 0.f;

    for (int cc = 0; cc < CIN; cc += 32) {
        for (int j = t; j < 32*64; j += 256) {
            int o = j >> 5, cr = j & 31;
            ws[cr*65 + o] = W[o*CIN + cc + cr];
        }
        for (int j = t; j < 32*128; j += 256) {
            int r = j >> 7, col = j & 127;
            xs[r*128 + col] = x[(size_t)(cc + r)*NTOK + n0 + col];
        }
        __syncthreads();
        if (t < 128) {
            #pragma unroll 8
            for (int r = 0; r < 32; r++) cs += xs[r*128 + t];
        }
        #pragma unroll 4
        for (int kc = 0; kc < 32; kc++) {
            float a[4], bb[8];
            #pragma unroll
            for (int u = 0; u < 4; u++) a[u] = ws[kc*65 + ty*4 + u];
            #pragma unroll
            for (int v = 0; v < 8; v++) bb[v] = xs[kc*128 + tx*8 + v];
            #pragma unroll
            for (int u = 0; u < 4; u++)
                #pragma unroll
                for (int v = 0; v < 8; v++)
                    acc[u][v] = fmaf(a[u], bb[v], acc[u][v]);
        }
        __syncthreads();
    }
    if (t < 128) minv[t] = cs * (1.f/CIN);
    __syncthreads();

    float* psum = pool;                // [16][128], ws/xs dead now
    float ssq[8];
    #pragma unroll
    for (int v = 0; v < 8; v++) ssq[v] = 0.f;
    #pragma unroll
    for (int u = 0; u < 4; u++) {
        int o = ty*4 + u;
        float wsm = g_wsum[o], sc = g_scale[o], bi = g_bias[o];
        #pragma unroll
        for (int v = 0; v < 8; v++) {
            float y = acc[u][v] - wsm * minv[tx*8 + v];
            y = fmaxf(y * sc + bi, 0.f);
            acc[u][v] = y;
            ssq[v] += y * y;
        }
    }
    #pragma unroll
    for (int v = 0; v < 8; v++) psum[ty*128 + tx*8 + v] = ssq[v];
    __syncthreads();
    if (t < 128) {
        float s = 0.f;
        #pragma unroll
        for (int r = 0; r < 16; r++) s += psum[r*128 + t];
        linv[t] = 1.f / fmaxf(sqrtf(s), L2_EPS);
        moutp[n0 + t] = minv[t];
    }
    __syncthreads();

    float* stg = pool;                 // [128][68], psum consumed
    #pragma unroll
    for (int u = 0; u < 4; u++) {
        int p = perm8(ty*4 + u);
        #pragma unroll
        for (int v = 0; v < 8; v++) {
            int col = tx*8 + v;
            stg[col*68 + p] = acc[u][v] * linv[col];
        }
    }
    __syncthreads();
    for (int idx = t; idx < 128*16; idx += 256) {
        int col = idx >> 4, c4 = (idx & 15) << 2;
        float4 val = *(float4*)&stg[col*68 + c4];
        *(float4*)(outp + (size_t)(n0 + col)*CP + c4) = val;
    }
}

/* ------------- K1: per-pair 512x512 corr via tf32 mma + row/col stats -------------
 * CTA tile: ib in {0,1} over 256 i-rows, kb in {0..3} over 128 j-cols.
 * 8 warps = 4(wi: 64 i) x 2(wj: 64 j). Warp tile 64x64 = 4 M-atoms x 8 N-atoms.
 */
#define K1_SMEM_BYTES ((256*68 + 128*68 + 128*33*2 + 256*9*2 + 1024) * 4)

extern "C" __global__ void __launch_bounds__(256, 1) kcorr() {
    extern __shared__ unsigned smu[];
    unsigned* Sm = smu;                      // [256][68] tf32
    unsigned* Qm = Sm + 256*68;              // [128][68] tf32
    float* cps = (float*)(Qm + 128*68);      // [128][33] col partial sums
    float* cpq = cps + 128*33;               // [128][33] col partial sumsq
    float* rps = cpq + 128*33;               // [256][9]  row partial sums
    float* rpq = rps + 256*9;                // [256][9]
    float* colsum = rpq + 256*9;             // [512]
    float* colsq  = colsum + 512;            // [512]

    int pair = blockIdx.x;
    int q = pair / WAY, w = pair % WAY;
    const float* Sg = g_S + (size_t)w*NTOK*CP;
    const float* Qg = g_Q + (size_t)q*NTOK*CP;
    float* Cb = g_C + (size_t)pair*NTOK*NTOK;

    int t = threadIdx.x, lane = t & 31, warp = t >> 5;
    int wi = warp >> 1, wj = warp & 1;
    int la = lane >> 2, lb = lane & 3;

    for (int j = t; j < 512; j += 256) { colsum[j] = 0.f; colsq[j] = 0.f; }

    for (int ib = 0; ib < 2; ib++) {
        __syncthreads();
        for (int idx = t; idx < 256*16; idx += 256) {
            int r = idx >> 4, c4 = (idx & 15) << 2;
            float4 v = *(const float4*)(Sg + (size_t)(ib*256 + r)*CP + c4);
            uint4 u = make_uint4(to_tf32(v.x), to_tf32(v.y), to_tf32(v.z), to_tf32(v.w));
            *(uint4*)(Sm + r*68 + c4) = u;
        }

        float rsum[4][2], rsq[4][2];
        #pragma unroll
        for (int m = 0; m < 4; m++) { rsum[m][0]=rsum[m][1]=0.f; rsq[m][0]=rsq[m][1]=0.f; }

        for (int kb = 0; kb < 4; kb++) {
            __syncthreads();
            for (int idx = t; idx < 128*16; idx += 256) {
                int r = idx >> 4, c4 = (idx & 15) << 2;
                float4 v = *(const float4*)(Qg + (size_t)(kb*128 + r)*CP + c4);
                uint4 u = make_uint4(to_tf32(v.x), to_tf32(v.y), to_tf32(v.z), to_tf32(v.w));
                *(uint4*)(Qm + r*68 + c4) = u;
            }
            __syncthreads();

            float acc[4][8][4];
            #pragma unroll
            for (int m = 0; m < 4; m++)
                #pragma unroll
                for (int n = 0; n < 8; n++)
                    #pragma unroll
                    for (int e = 0; e < 4; e++) acc[m][n][e] = 0.f;

            #pragma unroll 2
            for (int ks = 0; ks < 8; ks++) {
                int k0 = ks*8 + 2*lb;
                uint2 af[4][2];
                #pragma unroll
                for (int m = 0; m < 4; m++) {
                    int r0 = wi*64 + m*16 + la;
                    af[m][0] = *(uint2*)(Sm + r0*68 + k0);
                    af[m][1] = *(uint2*)(Sm + (r0+8)*68 + k0);
                }
                uint2 bf[8];
                #pragma unroll
                for (int n = 0; n < 8; n++) {
                    int j0 = wj*64 + n*8 + la;
                    bf[n] = *(uint2*)(Qm + j0*68 + k0);
                }
                #pragma unroll
                for (int m = 0; m < 4; m++)
                    #pragma unroll
                    for (int n = 0; n < 8; n++)
                        mma_tf32(acc[m][n], af[m][0].x, af[m][1].x,
                                 af[m][0].y, af[m][1].y, bf[n].x, bf[n].y);
            }

            /* store C subtile (float2 per row-frag) */
            float* Ct = Cb + kb*128 + wj*64;
            #pragma unroll
            for (int m = 0; m < 4; m++) {
                int r0 = ib*256 + wi*64 + m*16 + la;
                #pragma unroll
                for (int n = 0; n < 8; n++) {
                    int c0 = n*8 + 2*lb;
                    *(float2*)(Ct + (size_t)r0*NTOK + c0)     = make_float2(acc[m][n][0], acc[m][n][1]);
                    *(float2*)(Ct + (size_t)(r0+8)*NTOK + c0) = make_float2(acc[m][n][2], acc[m][n][3]);
                }
            }

            /* row partial accumulate (regs, across kb) */
            #pragma unroll
            for (int m = 0; m < 4; m++)
                #pragma unroll
                for (int h = 0; h < 2; h++) {
                    float s = 0.f, ss = 0.f;
                    #pragma unroll
                    for (int n = 0; n < 8; n++)
                        #pragma unroll
                        for (int p = 0; p < 2; p++) {
                            float v = acc[m][n][2*h + p];
                            s += v; ss += v*v;
                        }
                    rsum[m][h] += s; rsq[m][h] += ss;
                }

            /* col partials -> smem */
            #pragma unroll
            for (int n = 0; n < 8; n++)
                #pragma unroll
                for (int p = 0; p < 2; p++) {
                    float s = 0.f, ss = 0.f;
                    #pragma unroll
                    for (int m = 0; m < 4; m++)
                        #pragma unroll
                        for (int h = 0; h < 2; h++) {
                            float v = acc[m][n][2*h + p];
                            s += v; ss += v*v;
                        }
                    int cl = wj*64 + n*8 + 2*lb + p;
                    cps[cl*33 + wi*8 + la] = s;
                    cpq[cl*33 + wi*8 + la] = ss;
                }
            __syncthreads();
            if (t < 128) {
                float s = 0.f, ss = 0.f;
                #pragma unroll 8
                for (int c = 0; c < 32; c++) { s += cps[t*33 + c]; ss += cpq[t*33 + c]; }
                colsum[kb*128 + t] += s;
                colsq [kb*128 + t] += ss;
            }
        }

        __syncthreads();
        #pragma unroll
        for (int m = 0; m < 4; m++)
            #pragma unroll
            for (int h = 0; h < 2; h++) {
                int rl = wi*64 + m*16 + la + 8*h;
                rps[rl*9 + wj*4 + lb] = rsum[m][h];
                rpq[rl*9 + wj*4 + lb] = rsq[m][h];
            }
        __syncthreads();
        {
            float s = 0.f, ss = 0.f;
            #pragma unroll
            for (int c = 0; c < 8; c++) { s += rps[t*9 + c]; ss += rpq[t*9 + c]; }
            float m_ = s * (1.f/512.f);
            float var = fmaxf(ss - s*m_, 0.f) * (1.f/511.f);
            g_rm[pair*NTOK + ib*256 + t] = m_;
            g_ri[pair*NTOK + ib*256 + t] = LOG2E / (5.f * sqrtf(var + GN_EPS));
        }
    }
    __syncthreads();
    for (int j = t; j < 512; j += 256) {
        float s = colsum[j], sq = colsq[j];
        float m_ = s * (1.f/512.f);
        float var = fmaxf(sq - s*m_, 0.f) * (1.f/511.f);
        g_cm[pair*NTOK + j] = m_;
        g_ci[pair*NTOK + j] = LOG2E / (5.f * sqrtf(var + GN_EPS));
    }
}

/* ------------- K2: bidirectional softmax sums, 16-row chunks for occupancy ------------- */
__global__ __launch_bounds__(256) void kattn() {
    __shared__ float ri_s[512], rofs[512], rzq[512];
    __shared__ float rowbuf[16][257];
    __shared__ float part[16][17];

    int pair = blockIdx.x;
    int t = threadIdx.x;
    int rr = t & 15, gg = t >> 4;

    for (int j = t; j < 512; j += 256) {
        float m = g_rm[pair*NTOK + j], s = g_ri[pair*NTOK + j];
        ri_s[j] = s;  rofs[j] = m * s;
    }
    float cix = g_ci[pair*NTOK + 2*t],   cmx = g_cm[pair*NTOK + 2*t]   * cix;
    float ciy = g_ci[pair*NTOK + 2*t+1], cmy = g_cm[pair*NTOK + 2*t+1] * ciy;
    __syncthreads();

    const float2* C2 = (const float2*)(g_C + (size_t)pair*NTOK*NTOK);

    /* pass A: Z sums */
    float zs0 = 0.f, zs1 = 0.f;
    for (int i0 = 0; i0 < 512; i0 += 16) {
        #pragma unroll
        for (int r = 0; r < 16; r++) {
            float2 c = C2[(size_t)(i0 + r)*256 + t];
            float es0 = ex2(fmaf(c.x, cix, -cmx));
            float es1 = ex2(fmaf(c.y, ciy, -cmy));
            float rs = ri_s[i0 + r], ro = rofs[i0 + r];
            float eq0 = ex2(fmaf(c.x, rs, -ro));
            float eq1 = ex2(fmaf(c.y, rs, -ro));
            zs0 += es0; zs1 += es1;
            rowbuf[r][t] = eq0 + eq1;
        }
        __syncthreads();
        {
            float s = 0.f;
            #pragma unroll
            for (int j = 0; j < 16; j++) s += rowbuf[rr][gg*16 + j];
            part[rr][gg] = s;
        }
        __syncthreads();
        if (t < 16) {
            float z = 0.f;
            #pragma unroll
            for (int g = 0; g < 16; g++) z += part[t][g];
            rzq[i0 + t] = 1.f / z;
        }
        __syncthreads();
    }
    float rz0 = 1.f / zs0, rz1 = 1.f / zs1;

    /* pass B: attention sums */
    float aq0 = 0.f, aq1 = 0.f;
    for (int i0 = 0; i0 < 512; i0 += 16) {
        #pragma unroll
        for (int r = 0; r < 16; r++) {
            float2 c = C2[(size_t)(i0 + r)*256 + t];
            float es0 = ex2(fmaf(c.x, cix, -cmx));
            float es1 = ex2(fmaf(c.y, ciy, -cmy));
            float rs = ri_s[i0 + r], ro = rofs[i0 + r];
            float eq0 = ex2(fmaf(c.x, rs, -ro));
            float eq1 = ex2(fmaf(c.y, rs, -ro));
            float rq = rzq[i0 + r];
            aq0 = fmaf(eq0, rq, aq0);
            aq1 = fmaf(eq1, rq, aq1);
            rowbuf[r][t] = fmaf(es0, rz0, es1 * rz1);
        }
        __syncthreads();
        {
            float s = 0.f;
            #pragma unroll
            for (int j = 0; j < 16; j++) s += rowbuf[rr][gg*16 + j];
            part[rr][gg] = s;
        }
        __syncthreads();
        if (t < 16) {
            float s = 0.f;
            #pragma unroll
            for (int g = 0; g < 16; g++) s += part[t][g];
            g_as[pair*NTOK + i0 + t] = s;
        }
        __syncthreads();
    }
    g_aq[pair*NTOK + 2*t]   = aq0;
    g_aq[pair*NTOK + 2*t+1] = aq1;
}

/* ------------- K3: attention-weighted pooling + cosine sim ------------- */
__global__ __launch_bounds__(256) void kfinal(const float* __restrict__ sup,
                                              const float* __restrict__ qry,
                                              float* __restrict__ out) {
    __shared__ float as_[512], aq_[512], ms[512], mq[512];
    __shared__ float ps[CIN], pq[CIN];
    __shared__ float rbuf[256];

    int pair = blockIdx.x;
    int q = pair / WAY, w = pair % WAY;
    int t = threadIdx.x, warp = t >> 5, lane = t & 31;

    for (int j = t; j < 512; j += 256) {
        as_[j] = g_as[pair*NTOK + j];
        aq_[j] = g_aq[pair*NTOK + j];
        ms[j]  = g_mS[w*NTOK + j];
        mq[j]  = g_mQ[q*NTOK + j];
    }
    __syncthreads();

    const float* xs = sup + (size_t)w*CIN*NTOK;
    const float* xq = qry + (size_t)q*CIN*NTOK;

    for (int c = warp; c < CIN; c += 8) {
        float v = 0.f, v2 = 0.f;
        #pragma unroll 4
        for (int i = lane; i < 512; i += 32) {
            v  += as_[i] * (xs[(size_t)c*NTOK + i] - ms[i]);
            v2 += aq_[i] * (xq[(size_t)c*NTOK + i] - mq[i]);
        }
        v  = warp_sum(v);
        v2 = warp_sum(v2);
        if (lane == 0) { ps[c] = v; pq[c] = v2; }
    }
    __syncthreads();

    float dp = 0.f, ns = 0.f, nq2 = 0.f;
    for (int c = t; c < CIN; c += 256) {
        float a = ps[c], b = pq[c];
        dp += a*b; ns += a*a; nq2 += b*b;
    }
    float vals[3] = {dp, ns, nq2};
    float red3[3];
    for (int r = 0; r < 3; r++) {
        rbuf[t] = vals[r];
        __syncthreads();
        for (int s = 128; s > 0; s >>= 1) {
            if (t < s) rbuf[t] += rbuf[t + s];
            __syncthreads();
        }
        red3[r] = rbuf[0];
        __syncthreads();
    }
    if (t == 0) {
        float psn = fmaxf(sqrtf(red3[1]) * (1.f/512.f), L2_EPS);
        float pqn = fmaxf(sqrtf(red3[2]) * (1.f/512.f), L2_EPS);
        float sim = (red3[0] * (1.f/(512.f*512.f))) / (psn * pqn);
        out[pair] = sim * 5.f;
    }
}

/* ------------- launcher ------------- */
extern "C" void kernel_launch(void* const* d_in, const int* in_sizes, int n_in,
                              void* d_out, int out_size) {
    const float* sup   = (const float*)d_in[0];
    const float* qry   = (const float*)d_in[1];
    const float* W     = (const float*)d_in[2];
    const float* gamma = (const float*)d_in[3];
    const float* beta  = (const float*)d_in[4];
    const float* mean  = (const float*)d_in[5];
    const float* var   = (const float*)d_in[6];
    float* out = (float*)d_out;

    cudaFuncSetAttribute(kcorr, cudaFuncAttributeMaxDynamicSharedMemorySize, K1_SMEM_BYTES);

    kpre<<<1, 64>>>(W, gamma, beta, mean, var);
    kproj<<<(WAY+NQ)*4, 256>>>(sup, qry, W);
    kcorr<<<PAIRS, 256, K1_SMEM_BYTES>>>();
    kattn<<<PAIRS, 256>>>();
    kfinal<<<PAIRS, 256>>>(sup, qry, out);
}